// round 14
// baseline (speedup 1.0000x reference)
#include <cuda_runtime.h>
#include <cuda_fp16.h>
#include <math.h>
#include <stdint.h>

#define HID  128
#define NCOL 256
#define MAX_NODES 100000
#define TILE_M 64
#define PADK 136             // fp16 row stride in smem (272B -> conflict-free ldmatrix)
#define K1_GRID 296

// Y (fp16), 51.2 MB. PERMUTED column layout (per 128-col half):
//   physical q = qnw*64 + qc*32 + qtig*8 + qnt4*2 + b
//   logical  j = qnw*64 + (qc*4+qnt4)*8 + qtig*2 + b
// b1/2 folded into both halves.
__device__ __half g_Yh[(size_t)MAX_NODES * NCOL];

#define A_ELEMS (TILE_M * PADK)     // 8704 halves (per buffer)
#define B_ELEMS (NCOL * PADK)       // 34816 halves
#define SMEM_BYTES ((2 * A_ELEMS + B_ELEMS) * 2 + 512)   // 104960 B -> 2 CTAs/SM

static __device__ __forceinline__ uint32_t packh2(float a, float b) {
    __half2 p = __floats2half2_rn(a, b);
    return *reinterpret_cast<uint32_t*>(&p);
}
static __device__ __forceinline__ uint32_t smem_u32(const void* p) {
    uint32_t a;
    asm("{ .reg .u64 t; cvta.to.shared.u64 t, %1; cvt.u32.u64 %0, t; }" : "=r"(a) : "l"(p));
    return a;
}
static __device__ __forceinline__ void hmma(float* d, const uint32_t* a, const uint32_t* b) {
    asm volatile(
        "mma.sync.aligned.m16n8k16.row.col.f32.f16.f16.f32 "
        "{%0,%1,%2,%3}, {%4,%5,%6,%7}, {%8,%9}, {%0,%1,%2,%3};"
        : "+f"(d[0]), "+f"(d[1]), "+f"(d[2]), "+f"(d[3])
        : "r"(a[0]), "r"(a[1]), "r"(a[2]), "r"(a[3]), "r"(b[0]), "r"(b[1]));
}
#define LDM_X4(r0, r1, r2, r3, addr) \
    asm volatile("ldmatrix.sync.aligned.m8n8.x4.shared.b16 {%0,%1,%2,%3}, [%4];" \
                 : "=r"(r0), "=r"(r1), "=r"(r2), "=r"(r3) : "r"(addr))

static __device__ __forceinline__ uint64_t evict_last_policy() {
    uint64_t p;
    asm("createpolicy.fractional.L2::evict_last.b64 %0, 1.0;" : "=l"(p));
    return p;
}
static __device__ __forceinline__ void stg_pol(__half* p, uint4 v, uint64_t pol) {
    asm volatile("st.global.L2::cache_hint.v4.u32 [%0], {%1,%2,%3,%4}, %5;"
                 :: "l"(p), "r"(v.x), "r"(v.y), "r"(v.z), "r"(v.w), "l"(pol) : "memory");
}

// ---------------------------------------------------------------------------
// K1: persistent, A double-buffered (register prefetch overlaps MMA).
// Epilogue stores use the evict_last policy (measured ~3-4us faster).
// ---------------------------------------------------------------------------
__global__ __launch_bounds__(256, 2)
void precompute_mma(const float* __restrict__ h,
                    const float* __restrict__ W1,
                    const float* __restrict__ b1,
                    int n_nodes, int n_tiles)
{
    extern __shared__ __align__(16) uint16_t smem[];
    uint16_t* Ah  = smem;                       // 2 buffers of A_ELEMS
    uint16_t* Bh  = Ah + 2 * A_ELEMS;
    float*    b1s = reinterpret_cast<float*>(Bh + B_ELEMS);

    const int tid  = threadIdx.x;
    const int w    = tid >> 5;
    const int lane = tid & 31;
    const uint64_t pol = evict_last_policy();

    #pragma unroll
    for (int idx = tid; idx < NCOL * 32; idx += 256) {
        const int r = idx >> 5, c = idx & 31;
        const float4* wr = reinterpret_cast<const float4*>(
            W1 + (size_t)(r & 127) * (2 * HID) + ((r >> 7) * HID));
        float4 f = wr[c];
        *reinterpret_cast<uint2*>(Bh + r * PADK + c * 4) =
            make_uint2(packh2(f.x, f.y), packh2(f.z, f.w));
    }
    if (tid < HID) b1s[tid] = b1[tid] * 0.5f;

    const int g   = lane >> 2;
    const int tig = lane & 3;
    const int mwarp = (w & 1) * 32;
    const int nwarp = (w >> 1) * 64;

    uint32_t a_addr0[2], b_addr[4];
    {
        const uint32_t sA = smem_u32(Ah), sB = smem_u32(Bh);
        #pragma unroll
        for (int mt = 0; mt < 2; mt++) {
            const int row = mwarp + mt * 16 + (lane & 15);
            a_addr0[mt] = sA + (uint32_t)(row * PADK + ((lane >> 4) & 1) * 8) * 2;
        }
        #pragma unroll
        for (int p = 0; p < 4; p++) {
            const int rn = nwarp + p * 16 + (lane & 7) + ((lane >> 4) & 1) * 8;
            b_addr[p] = sB + (uint32_t)(rn * PADK + ((lane >> 3) & 1) * 8) * 2;
        }
    }

    const float4* h4 = reinterpret_cast<const float4*>(h);
    const int c4   = tid & 31;
    const int row0 = tid >> 5;

    float4 pf[8];
    auto load_pf = [&](int tt) {
        #pragma unroll
        for (int k = 0; k < 8; k++) {
            const int m = tt * TILE_M + row0 + k * 8;
            pf[k] = (tt < n_tiles && m < n_nodes)
                  ? __ldcs(&h4[(size_t)m * 32 + c4])
                  : make_float4(0.f, 0.f, 0.f, 0.f);
        }
    };
    auto sts_pf = [&](uint16_t* buf) {
        #pragma unroll
        for (int k = 0; k < 8; k++)
            *reinterpret_cast<uint2*>(buf + (row0 + k * 8) * PADK + c4 * 4) =
                make_uint2(packh2(pf[k].x, pf[k].y), packh2(pf[k].z, pf[k].w));
    };

    int t = blockIdx.x;
    if (t < n_tiles) {
        load_pf(t);
        sts_pf(Ah);
    }
    __syncthreads();

    int buf = 0;
    while (t < n_tiles) {
        const int tn = t + (int)gridDim.x;
        load_pf(tn);                       // prefetch overlaps the MMA phase

        const uint32_t abase = (uint32_t)buf * (A_ELEMS * 2);
        float acc[2][8][4];
        #pragma unroll
        for (int mt = 0; mt < 2; mt++)
            #pragma unroll
            for (int nt = 0; nt < 8; nt++)
                #pragma unroll
                for (int r = 0; r < 4; r++) acc[mt][nt][r] = 0.f;

        #pragma unroll
        for (int kb = 0; kb < 8; kb++) {
            const uint32_t ko = (uint32_t)kb * 32;
            uint32_t ah[2][4];
            #pragma unroll
            for (int mt = 0; mt < 2; mt++)
                LDM_X4(ah[mt][0], ah[mt][1], ah[mt][2], ah[mt][3],
                       a_addr0[mt] + abase + ko);
            uint32_t bh[8][2];
            #pragma unroll
            for (int p = 0; p < 4; p++)
                LDM_X4(bh[2*p][0], bh[2*p][1], bh[2*p+1][0], bh[2*p+1][1], b_addr[p] + ko);
            #pragma unroll
            for (int mt = 0; mt < 2; mt++)
                #pragma unroll
                for (int nt = 0; nt < 8; nt++)
                    hmma(acc[mt][nt], ah[mt], bh[nt]);
        }

        const int m0 = t * TILE_M;
        #pragma unroll
        for (int mt = 0; mt < 2; mt++) {
            const int r0 = m0 + mwarp + mt * 16 + g;
            const int r1 = r0 + 8;
            #pragma unroll
            for (int c = 0; c < 2; c++) {
                uint4 s0, s1;
                __half2* h0 = reinterpret_cast<__half2*>(&s0);
                __half2* h1 = reinterpret_cast<__half2*>(&s1);
                #pragma unroll
                for (int q = 0; q < 4; q++) {
                    const int nt = c * 4 + q;
                    const int bcol = (nwarp + nt * 8 + tig * 2) & (HID - 1);
                    const float2 bb = *reinterpret_cast<const float2*>(&b1s[bcol]);
                    h0[q] = __floats2half2_rn(acc[mt][nt][0] + bb.x, acc[mt][nt][1] + bb.y);
                    h1[q] = __floats2half2_rn(acc[mt][nt][2] + bb.x, acc[mt][nt][3] + bb.y);
                }
                const uint32_t off = (uint32_t)nwarp + c * 32 + tig * 8;
                if (r0 < n_nodes) stg_pol(g_Yh + (size_t)r0 * NCOL + off, s0, pol);
                if (r1 < n_nodes) stg_pol(g_Yh + (size_t)r1 * NCOL + off, s1, pol);
            }
        }

        sts_pf(buf ? Ah : Ah + A_ELEMS);   // fill the other buffer
        __syncthreads();
        buf ^= 1;
        t = tn;
    }
}

// ---------------------------------------------------------------------------
// K2: round-12 version (measured 25.4us): 8 lanes/edge, 8 edges/warp-iter,
// half2 math, plain vector loads, 6 CTAs/SM. NO prefetch.
// ---------------------------------------------------------------------------
__global__ __launch_bounds__(256, 6)
void edge_kernel(const int* __restrict__ src,
                 const int* __restrict__ dst,
                 const float* __restrict__ W2,
                 const float* __restrict__ b2,
                 const float* __restrict__ W3,
                 const float* __restrict__ b3,
                 float* __restrict__ out,
                 int E)
{
    const int lane = threadIdx.x & 31;
    const int sub  = lane >> 3;
    const int l8   = lane & 7;
    const int wid  = (blockIdx.x * blockDim.x + threadIdx.x) >> 5;
    const int nwarps = (gridDim.x * blockDim.x) >> 5;

    // lane features (physical within-half): i<4 -> q=l8*8+i*2 ; i>=4 -> q=64+l8*8+(i-4)*2
    __half2 w2h[8];
    #pragma unroll
    for (int i = 0; i < 8; i++) {
        const int q   = (i < 4) ? (l8 * 8 + i * 2) : (64 + l8 * 8 + (i - 4) * 2);
        const int qnw = q >> 6, qc = (q >> 5) & 1, qtig = (q >> 3) & 3, qnt4 = (q >> 1) & 3;
        const int j   = qnw * 64 + (qc * 4 + qnt4) * 8 + qtig * 2;
        w2h[i] = __floats2half2_rn(W2[j], W2[j + 1]);
    }
    const float c2 = b2[0];
    const float w3 = W3[0];
    const float c3 = b3[0];
    const __half2 zero2 = __floats2half2_rn(0.f, 0.f);

    for (int e = wid * 8 + sub; ; e += nwarps * 8) {
        const int ebase = e - sub;
        if (ebase >= E) break;
        const int eA = (e < E) ? e : (E - 1);
        const int e2 = e + 4;
        const int eB = (e2 < E) ? e2 : (E - 1);

        const int sA = src[eA], dA = dst[eA];
        const int sB = src[eB], dB = dst[eB];

        const __half* YA_u = g_Yh + (uint32_t)sA * NCOL;
        const __half* YA_v = g_Yh + (uint32_t)dA * NCOL + HID;
        const __half* YB_u = g_Yh + (uint32_t)sB * NCOL;
        const __half* YB_v = g_Yh + (uint32_t)dB * NCOL + HID;

        uint4 ua0 = *reinterpret_cast<const uint4*>(YA_u + l8 * 8);
        uint4 ua1 = *reinterpret_cast<const uint4*>(YA_u + 64 + l8 * 8);
        uint4 va0 = *reinterpret_cast<const uint4*>(YA_v + l8 * 8);
        uint4 va1 = *reinterpret_cast<const uint4*>(YA_v + 64 + l8 * 8);
        uint4 ub0 = *reinterpret_cast<const uint4*>(YB_u + l8 * 8);
        uint4 ub1 = *reinterpret_cast<const uint4*>(YB_u + 64 + l8 * 8);
        uint4 vb0 = *reinterpret_cast<const uint4*>(YB_v + l8 * 8);
        uint4 vb1 = *reinterpret_cast<const uint4*>(YB_v + 64 + l8 * 8);

        const __half2* uhA0 = reinterpret_cast<const __half2*>(&ua0);
        const __half2* uhA1 = reinterpret_cast<const __half2*>(&ua1);
        const __half2* vhA0 = reinterpret_cast<const __half2*>(&va0);
        const __half2* vhA1 = reinterpret_cast<const __half2*>(&va1);
        const __half2* uhB0 = reinterpret_cast<const __half2*>(&ub0);
        const __half2* uhB1 = reinterpret_cast<const __half2*>(&ub1);
        const __half2* vhB0 = reinterpret_cast<const __half2*>(&vb0);
        const __half2* vhB1 = reinterpret_cast<const __half2*>(&vb1);

        __half2 accA = zero2, accB = zero2;
        #pragma unroll
        for (int i = 0; i < 4; i++) {
            __half2 xA = __hmax2(__hadd2(uhA0[i], vhA0[i]), zero2);
            accA = __hfma2(xA, w2h[i], accA);
            __half2 xB = __hmax2(__hadd2(uhB0[i], vhB0[i]), zero2);
            accB = __hfma2(xB, w2h[i], accB);
        }
        #pragma unroll
        for (int i = 0; i < 4; i++) {
            __half2 xA = __hmax2(__hadd2(uhA1[i], vhA1[i]), zero2);
            accA = __hfma2(xA, w2h[4 + i], accA);
            __half2 xB = __hmax2(__hadd2(uhB1[i], vhB1[i]), zero2);
            accB = __hfma2(xB, w2h[4 + i], accB);
        }

        float2 fA = __half22float2(accA);
        float2 fB = __half22float2(accB);
        float pA = fA.x + fA.y;
        float pB = fB.x + fB.y;

        pA += __shfl_xor_sync(0xFFFFFFFFu, pA, 1);
        pB += __shfl_xor_sync(0xFFFFFFFFu, pB, 1);
        pA += __shfl_xor_sync(0xFFFFFFFFu, pA, 2);
        pB += __shfl_xor_sync(0xFFFFFFFFu, pB, 2);
        pA += __shfl_xor_sync(0xFFFFFFFFu, pA, 4);
        pB += __shfl_xor_sync(0xFFFFFFFFu, pB, 4);

        if (l8 == 0) {
            if (e < E) {
                float s2 = fmaxf(pA + c2, 0.f);
                float s3 = fmaxf(fmaf(s2, w3, c3), 0.f);
                __stcs(&out[e], __fdividef(1.f, 1.f + __expf(-s3)));
            }
            if (e2 < E) {
                float s2 = fmaxf(pB + c2, 0.f);
                float s3 = fmaxf(fmaf(s2, w3, c3), 0.f);
                __stcs(&out[e2], __fdividef(1.f, 1.f + __expf(-s3)));
            }
        }
    }
}

// ---------------------------------------------------------------------------
extern "C" void kernel_launch(void* const* d_in, const int* in_sizes, int n_in,
                              void* d_out, int out_size)
{
    const float* h   = (const float*)d_in[0];
    const int*   src = (const int*)  d_in[1];
    const int*   dst = (const int*)  d_in[2];
    const float* W1  = (const float*)d_in[3];
    const float* b1  = (const float*)d_in[4];
    const float* W2  = (const float*)d_in[5];
    const float* b2  = (const float*)d_in[6];
    const float* W3  = (const float*)d_in[7];
    const float* b3  = (const float*)d_in[8];
    float* out = (float*)d_out;

    const int n_nodes = in_sizes[0] / HID;
    const int E       = in_sizes[1];
    const int n_tiles = (n_nodes + TILE_M - 1) / TILE_M;

    cudaFuncSetAttribute(precompute_mma,
                         cudaFuncAttributeMaxDynamicSharedMemorySize, SMEM_BYTES);

    precompute_mma<<<K1_GRID, 256, SMEM_BYTES>>>(h, W1, b1, n_nodes, n_tiles);
    edge_kernel<<<4096, 256>>>(src, dst, W2, b2, W3, b3, out, E);
}

// round 15
// speedup vs baseline: 1.3335x; 1.3335x over previous
#include <cuda_runtime.h>
#include <cuda_fp16.h>
#include <math.h>
#include <stdint.h>

#define HID  128
#define NCOL 256
#define MAX_NODES 100000
#define TILE_M 64
#define PADK 136             // fp16 row stride in smem (272B -> conflict-free ldmatrix)
#define K1_GRID 296

// Y (fp16), 51.2 MB. PERMUTED column layout (per 128-col half):
//   physical q = qnw*64 + qc*32 + qtig*8 + qnt4*2 + b
//   logical  j = qnw*64 + (qc*4+qnt4)*8 + qtig*2 + b
// b1/2 folded into both halves.
__device__ __half g_Yh[(size_t)MAX_NODES * NCOL];

#define A_ELEMS (TILE_M * PADK)     // 8704 halves (per buffer)
#define B_ELEMS (NCOL * PADK)       // 34816 halves
#define SMEM_BYTES ((2 * A_ELEMS + B_ELEMS) * 2 + 512)   // 104960 B -> 2 CTAs/SM

static __device__ __forceinline__ uint32_t packh2(float a, float b) {
    __half2 p = __floats2half2_rn(a, b);
    return *reinterpret_cast<uint32_t*>(&p);
}
static __device__ __forceinline__ uint32_t smem_u32(const void* p) {
    uint32_t a;
    asm("{ .reg .u64 t; cvta.to.shared.u64 t, %1; cvt.u32.u64 %0, t; }" : "=r"(a) : "l"(p));
    return a;
}
static __device__ __forceinline__ void hmma(float* d, const uint32_t* a, const uint32_t* b) {
    asm volatile(
        "mma.sync.aligned.m16n8k16.row.col.f32.f16.f16.f32 "
        "{%0,%1,%2,%3}, {%4,%5,%6,%7}, {%8,%9}, {%0,%1,%2,%3};"
        : "+f"(d[0]), "+f"(d[1]), "+f"(d[2]), "+f"(d[3])
        : "r"(a[0]), "r"(a[1]), "r"(a[2]), "r"(a[3]), "r"(b[0]), "r"(b[1]));
}
#define LDM_X4(r0, r1, r2, r3, addr) \
    asm volatile("ldmatrix.sync.aligned.m8n8.x4.shared.b16 {%0,%1,%2,%3}, [%4];" \
                 : "=r"(r0), "=r"(r1), "=r"(r2), "=r"(r3) : "r"(addr))

static __device__ __forceinline__ uint64_t evict_last_policy() {
    uint64_t p;
    asm("createpolicy.fractional.L2::evict_last.b64 %0, 1.0;" : "=l"(p));
    return p;
}
static __device__ __forceinline__ void stg_pol(__half* p, uint4 v, uint64_t pol) {
    asm volatile("st.global.L2::cache_hint.v4.u32 [%0], {%1,%2,%3,%4}, %5;"
                 :: "l"(p), "r"(v.x), "r"(v.y), "r"(v.z), "r"(v.w), "l"(pol) : "memory");
}

// ---------------------------------------------------------------------------
// K1: persistent, A double-buffered (register prefetch overlaps MMA).
// Epilogue stores use the evict_last policy (measured ~3-4us faster).
// ---------------------------------------------------------------------------
__global__ __launch_bounds__(256, 2)
void precompute_mma(const float* __restrict__ h,
                    const float* __restrict__ W1,
                    const float* __restrict__ b1,
                    int n_nodes, int n_tiles)
{
    extern __shared__ __align__(16) uint16_t smem[];
    uint16_t* Ah  = smem;                       // 2 buffers of A_ELEMS
    uint16_t* Bh  = Ah + 2 * A_ELEMS;
    float*    b1s = reinterpret_cast<float*>(Bh + B_ELEMS);

    const int tid  = threadIdx.x;
    const int w    = tid >> 5;
    const int lane = tid & 31;
    const uint64_t pol = evict_last_policy();

    #pragma unroll
    for (int idx = tid; idx < NCOL * 32; idx += 256) {
        const int r = idx >> 5, c = idx & 31;
        const float4* wr = reinterpret_cast<const float4*>(
            W1 + (size_t)(r & 127) * (2 * HID) + ((r >> 7) * HID));
        float4 f = wr[c];
        *reinterpret_cast<uint2*>(Bh + r * PADK + c * 4) =
            make_uint2(packh2(f.x, f.y), packh2(f.z, f.w));
    }
    if (tid < HID) b1s[tid] = b1[tid] * 0.5f;

    const int g   = lane >> 2;
    const int tig = lane & 3;
    const int mwarp = (w & 1) * 32;
    const int nwarp = (w >> 1) * 64;

    uint32_t a_addr0[2], b_addr[4];
    {
        const uint32_t sA = smem_u32(Ah), sB = smem_u32(Bh);
        #pragma unroll
        for (int mt = 0; mt < 2; mt++) {
            const int row = mwarp + mt * 16 + (lane & 15);
            a_addr0[mt] = sA + (uint32_t)(row * PADK + ((lane >> 4) & 1) * 8) * 2;
        }
        #pragma unroll
        for (int p = 0; p < 4; p++) {
            const int rn = nwarp + p * 16 + (lane & 7) + ((lane >> 4) & 1) * 8;
            b_addr[p] = sB + (uint32_t)(rn * PADK + ((lane >> 3) & 1) * 8) * 2;
        }
    }

    const float4* h4 = reinterpret_cast<const float4*>(h);
    const int c4   = tid & 31;
    const int row0 = tid >> 5;

    float4 pf[8];
    auto load_pf = [&](int tt) {
        #pragma unroll
        for (int k = 0; k < 8; k++) {
            const int m = tt * TILE_M + row0 + k * 8;
            pf[k] = (tt < n_tiles && m < n_nodes)
                  ? __ldcs(&h4[(size_t)m * 32 + c4])
                  : make_float4(0.f, 0.f, 0.f, 0.f);
        }
    };
    auto sts_pf = [&](uint16_t* buf) {
        #pragma unroll
        for (int k = 0; k < 8; k++)
            *reinterpret_cast<uint2*>(buf + (row0 + k * 8) * PADK + c4 * 4) =
                make_uint2(packh2(pf[k].x, pf[k].y), packh2(pf[k].z, pf[k].w));
    };

    int t = blockIdx.x;
    if (t < n_tiles) {
        load_pf(t);
        sts_pf(Ah);
    }
    __syncthreads();

    int buf = 0;
    while (t < n_tiles) {
        const int tn = t + (int)gridDim.x;
        load_pf(tn);                       // prefetch overlaps the MMA phase

        const uint32_t abase = (uint32_t)buf * (A_ELEMS * 2);
        float acc[2][8][4];
        #pragma unroll
        for (int mt = 0; mt < 2; mt++)
            #pragma unroll
            for (int nt = 0; nt < 8; nt++)
                #pragma unroll
                for (int r = 0; r < 4; r++) acc[mt][nt][r] = 0.f;

        #pragma unroll
        for (int kb = 0; kb < 8; kb++) {
            const uint32_t ko = (uint32_t)kb * 32;
            uint32_t ah[2][4];
            #pragma unroll
            for (int mt = 0; mt < 2; mt++)
                LDM_X4(ah[mt][0], ah[mt][1], ah[mt][2], ah[mt][3],
                       a_addr0[mt] + abase + ko);
            uint32_t bh[8][2];
            #pragma unroll
            for (int p = 0; p < 4; p++)
                LDM_X4(bh[2*p][0], bh[2*p][1], bh[2*p+1][0], bh[2*p+1][1], b_addr[p] + ko);
            #pragma unroll
            for (int mt = 0; mt < 2; mt++)
                #pragma unroll
                for (int nt = 0; nt < 8; nt++)
                    hmma(acc[mt][nt], ah[mt], bh[nt]);
        }

        const int m0 = t * TILE_M;
        #pragma unroll
        for (int mt = 0; mt < 2; mt++) {
            const int r0 = m0 + mwarp + mt * 16 + g;
            const int r1 = r0 + 8;
            #pragma unroll
            for (int c = 0; c < 2; c++) {
                uint4 s0, s1;
                __half2* h0 = reinterpret_cast<__half2*>(&s0);
                __half2* h1 = reinterpret_cast<__half2*>(&s1);
                #pragma unroll
                for (int q = 0; q < 4; q++) {
                    const int nt = c * 4 + q;
                    const int bcol = (nwarp + nt * 8 + tig * 2) & (HID - 1);
                    const float2 bb = *reinterpret_cast<const float2*>(&b1s[bcol]);
                    h0[q] = __floats2half2_rn(acc[mt][nt][0] + bb.x, acc[mt][nt][1] + bb.y);
                    h1[q] = __floats2half2_rn(acc[mt][nt][2] + bb.x, acc[mt][nt][3] + bb.y);
                }
                const uint32_t off = (uint32_t)nwarp + c * 32 + tig * 8;
                if (r0 < n_nodes) stg_pol(g_Yh + (size_t)r0 * NCOL + off, s0, pol);
                if (r1 < n_nodes) stg_pol(g_Yh + (size_t)r1 * NCOL + off, s1, pol);
            }
        }

        sts_pf(buf ? Ah : Ah + A_ELEMS);   // fill the other buffer
        __syncthreads();
        buf ^= 1;
        t = tn;
    }
}

// ---------------------------------------------------------------------------
// K2: round-12 version (measured 25.4us): 8 lanes/edge, 8 edges/warp-iter,
// half2 math, plain vector loads, 6 CTAs/SM. NO prefetch.
// ---------------------------------------------------------------------------
__global__ __launch_bounds__(256, 6)
void edge_kernel(const int* __restrict__ src,
                 const int* __restrict__ dst,
                 const float* __restrict__ W2,
                 const float* __restrict__ b2,
                 const float* __restrict__ W3,
                 const float* __restrict__ b3,
                 float* __restrict__ out,
                 int E)
{
    const int lane = threadIdx.x & 31;
    const int sub  = lane >> 3;
    const int l8   = lane & 7;
    const int wid  = (blockIdx.x * blockDim.x + threadIdx.x) >> 5;
    const int nwarps = (gridDim.x * blockDim.x) >> 5;

    // lane features (physical within-half): i<4 -> q=l8*8+i*2 ; i>=4 -> q=64+l8*8+(i-4)*2
    __half2 w2h[8];
    #pragma unroll
    for (int i = 0; i < 8; i++) {
        const int q   = (i < 4) ? (l8 * 8 + i * 2) : (64 + l8 * 8 + (i - 4) * 2);
        const int qnw = q >> 6, qc = (q >> 5) & 1, qtig = (q >> 3) & 3, qnt4 = (q >> 1) & 3;
        const int j   = qnw * 64 + (qc * 4 + qnt4) * 8 + qtig * 2;
        w2h[i] = __floats2half2_rn(W2[j], W2[j + 1]);
    }
    const float c2 = b2[0];
    const float w3 = W3[0];
    const float c3 = b3[0];
    const __half2 zero2 = __floats2half2_rn(0.f, 0.f);

    for (int e = wid * 8 + sub; ; e += nwarps * 8) {
        const int ebase = e - sub;
        if (ebase >= E) break;
        const int eA = (e < E) ? e : (E - 1);
        const int e2 = e + 4;
        const int eB = (e2 < E) ? e2 : (E - 1);

        const int sA = src[eA], dA = dst[eA];
        const int sB = src[eB], dB = dst[eB];

        const __half* YA_u = g_Yh + (uint32_t)sA * NCOL;
        const __half* YA_v = g_Yh + (uint32_t)dA * NCOL + HID;
        const __half* YB_u = g_Yh + (uint32_t)sB * NCOL;
        const __half* YB_v = g_Yh + (uint32_t)dB * NCOL + HID;

        uint4 ua0 = *reinterpret_cast<const uint4*>(YA_u + l8 * 8);
        uint4 ua1 = *reinterpret_cast<const uint4*>(YA_u + 64 + l8 * 8);
        uint4 va0 = *reinterpret_cast<const uint4*>(YA_v + l8 * 8);
        uint4 va1 = *reinterpret_cast<const uint4*>(YA_v + 64 + l8 * 8);
        uint4 ub0 = *reinterpret_cast<const uint4*>(YB_u + l8 * 8);
        uint4 ub1 = *reinterpret_cast<const uint4*>(YB_u + 64 + l8 * 8);
        uint4 vb0 = *reinterpret_cast<const uint4*>(YB_v + l8 * 8);
        uint4 vb1 = *reinterpret_cast<const uint4*>(YB_v + 64 + l8 * 8);

        const __half2* uhA0 = reinterpret_cast<const __half2*>(&ua0);
        const __half2* uhA1 = reinterpret_cast<const __half2*>(&ua1);
        const __half2* vhA0 = reinterpret_cast<const __half2*>(&va0);
        const __half2* vhA1 = reinterpret_cast<const __half2*>(&va1);
        const __half2* uhB0 = reinterpret_cast<const __half2*>(&ub0);
        const __half2* uhB1 = reinterpret_cast<const __half2*>(&ub1);
        const __half2* vhB0 = reinterpret_cast<const __half2*>(&vb0);
        const __half2* vhB1 = reinterpret_cast<const __half2*>(&vb1);

        __half2 accA = zero2, accB = zero2;
        #pragma unroll
        for (int i = 0; i < 4; i++) {
            __half2 xA = __hmax2(__hadd2(uhA0[i], vhA0[i]), zero2);
            accA = __hfma2(xA, w2h[i], accA);
            __half2 xB = __hmax2(__hadd2(uhB0[i], vhB0[i]), zero2);
            accB = __hfma2(xB, w2h[i], accB);
        }
        #pragma unroll
        for (int i = 0; i < 4; i++) {
            __half2 xA = __hmax2(__hadd2(uhA1[i], vhA1[i]), zero2);
            accA = __hfma2(xA, w2h[4 + i], accA);
            __half2 xB = __hmax2(__hadd2(uhB1[i], vhB1[i]), zero2);
            accB = __hfma2(xB, w2h[4 + i], accB);
        }

        float2 fA = __half22float2(accA);
        float2 fB = __half22float2(accB);
        float pA = fA.x + fA.y;
        float pB = fB.x + fB.y;

        pA += __shfl_xor_sync(0xFFFFFFFFu, pA, 1);
        pB += __shfl_xor_sync(0xFFFFFFFFu, pB, 1);
        pA += __shfl_xor_sync(0xFFFFFFFFu, pA, 2);
        pB += __shfl_xor_sync(0xFFFFFFFFu, pB, 2);
        pA += __shfl_xor_sync(0xFFFFFFFFu, pA, 4);
        pB += __shfl_xor_sync(0xFFFFFFFFu, pB, 4);

        if (l8 == 0) {
            if (e < E) {
                float s2 = fmaxf(pA + c2, 0.f);
                float s3 = fmaxf(fmaf(s2, w3, c3), 0.f);
                __stcs(&out[e], __fdividef(1.f, 1.f + __expf(-s3)));
            }
            if (e2 < E) {
                float s2 = fmaxf(pB + c2, 0.f);
                float s3 = fmaxf(fmaf(s2, w3, c3), 0.f);
                __stcs(&out[e2], __fdividef(1.f, 1.f + __expf(-s3)));
            }
        }
    }
}

// ---------------------------------------------------------------------------
extern "C" void kernel_launch(void* const* d_in, const int* in_sizes, int n_in,
                              void* d_out, int out_size)
{
    const float* h   = (const float*)d_in[0];
    const int*   src = (const int*)  d_in[1];
    const int*   dst = (const int*)  d_in[2];
    const float* W1  = (const float*)d_in[3];
    const float* b1  = (const float*)d_in[4];
    const float* W2  = (const float*)d_in[5];
    const float* b2  = (const float*)d_in[6];
    const float* W3  = (const float*)d_in[7];
    const float* b3  = (const float*)d_in[8];
    float* out = (float*)d_out;

    const int n_nodes = in_sizes[0] / HID;
    const int E       = in_sizes[1];
    const int n_tiles = (n_nodes + TILE_M - 1) / TILE_M;

    cudaFuncSetAttribute(precompute_mma,
                         cudaFuncAttributeMaxDynamicSharedMemorySize, SMEM_BYTES);

    precompute_mma<<<K1_GRID, 256, SMEM_BYTES>>>(h, W1, b1, n_nodes, n_tiles);
    edge_kernel<<<4096, 256>>>(src, dst, W2, b2, W3, b3, out, E);
}

// round 16
// speedup vs baseline: 1.3443x; 1.0081x over previous
#include <cuda_runtime.h>
#include <cuda_fp16.h>
#include <math.h>
#include <stdint.h>

#define HID  128
#define NCOL 256
#define MAX_NODES 100000
#define TILE_M 64
#define PADK 136             // fp16 row stride in smem (272B -> conflict-free ldmatrix)
#define K1_GRID 296
#define K2_GRID 888          // 148 SMs x 6 CTAs/SM -> one resident wave
#define K2_BLOCK 128

// Y (fp16), 51.2 MB. PERMUTED column layout (per 128-col half):
//   physical q = qnw*64 + qc*32 + qtig*8 + qnt4*2 + b
//   logical  j = qnw*64 + (qc*4+qnt4)*8 + qtig*2 + b
// b1/2 folded into both halves.
__device__ __half g_Yh[(size_t)MAX_NODES * NCOL];

#define A_ELEMS (TILE_M * PADK)     // 8704 halves (per buffer)
#define B_ELEMS (NCOL * PADK)       // 34816 halves
#define SMEM_BYTES ((2 * A_ELEMS + B_ELEMS) * 2 + 512)   // 104960 B -> 2 CTAs/SM

static __device__ __forceinline__ uint32_t packh2(float a, float b) {
    __half2 p = __floats2half2_rn(a, b);
    return *reinterpret_cast<uint32_t*>(&p);
}
static __device__ __forceinline__ uint32_t smem_u32(const void* p) {
    uint32_t a;
    asm("{ .reg .u64 t; cvta.to.shared.u64 t, %1; cvt.u32.u64 %0, t; }" : "=r"(a) : "l"(p));
    return a;
}
static __device__ __forceinline__ void hmma(float* d, const uint32_t* a, const uint32_t* b) {
    asm volatile(
        "mma.sync.aligned.m16n8k16.row.col.f32.f16.f16.f32 "
        "{%0,%1,%2,%3}, {%4,%5,%6,%7}, {%8,%9}, {%0,%1,%2,%3};"
        : "+f"(d[0]), "+f"(d[1]), "+f"(d[2]), "+f"(d[3])
        : "r"(a[0]), "r"(a[1]), "r"(a[2]), "r"(a[3]), "r"(b[0]), "r"(b[1]));
}
#define LDM_X4(r0, r1, r2, r3, addr) \
    asm volatile("ldmatrix.sync.aligned.m8n8.x4.shared.b16 {%0,%1,%2,%3}, [%4];" \
                 : "=r"(r0), "=r"(r1), "=r"(r2), "=r"(r3) : "r"(addr))

static __device__ __forceinline__ uint64_t evict_last_policy() {
    uint64_t p;
    asm("createpolicy.fractional.L2::evict_last.b64 %0, 1.0;" : "=l"(p));
    return p;
}
static __device__ __forceinline__ void stg_pol(__half* p, uint4 v, uint64_t pol) {
    asm volatile("st.global.L2::cache_hint.v4.u32 [%0], {%1,%2,%3,%4}, %5;"
                 :: "l"(p), "r"(v.x), "r"(v.y), "r"(v.z), "r"(v.w), "l"(pol) : "memory");
}

// ---------------------------------------------------------------------------
// K1: persistent, A double-buffered (register prefetch overlaps MMA).
// Epilogue stores use the evict_last policy (measured ~3-4us faster).
// ---------------------------------------------------------------------------
__global__ __launch_bounds__(256, 2)
void precompute_mma(const float* __restrict__ h,
                    const float* __restrict__ W1,
                    const float* __restrict__ b1,
                    int n_nodes, int n_tiles)
{
    extern __shared__ __align__(16) uint16_t smem[];
    uint16_t* Ah  = smem;                       // 2 buffers of A_ELEMS
    uint16_t* Bh  = Ah + 2 * A_ELEMS;
    float*    b1s = reinterpret_cast<float*>(Bh + B_ELEMS);

    const int tid  = threadIdx.x;
    const int w    = tid >> 5;
    const int lane = tid & 31;
    const uint64_t pol = evict_last_policy();

    #pragma unroll
    for (int idx = tid; idx < NCOL * 32; idx += 256) {
        const int r = idx >> 5, c = idx & 31;
        const float4* wr = reinterpret_cast<const float4*>(
            W1 + (size_t)(r & 127) * (2 * HID) + ((r >> 7) * HID));
        float4 f = wr[c];
        *reinterpret_cast<uint2*>(Bh + r * PADK + c * 4) =
            make_uint2(packh2(f.x, f.y), packh2(f.z, f.w));
    }
    if (tid < HID) b1s[tid] = b1[tid] * 0.5f;

    const int g   = lane >> 2;
    const int tig = lane & 3;
    const int mwarp = (w & 1) * 32;
    const int nwarp = (w >> 1) * 64;

    uint32_t a_addr0[2], b_addr[4];
    {
        const uint32_t sA = smem_u32(Ah), sB = smem_u32(Bh);
        #pragma unroll
        for (int mt = 0; mt < 2; mt++) {
            const int row = mwarp + mt * 16 + (lane & 15);
            a_addr0[mt] = sA + (uint32_t)(row * PADK + ((lane >> 4) & 1) * 8) * 2;
        }
        #pragma unroll
        for (int p = 0; p < 4; p++) {
            const int rn = nwarp + p * 16 + (lane & 7) + ((lane >> 4) & 1) * 8;
            b_addr[p] = sB + (uint32_t)(rn * PADK + ((lane >> 3) & 1) * 8) * 2;
        }
    }

    const float4* h4 = reinterpret_cast<const float4*>(h);
    const int c4   = tid & 31;
    const int row0 = tid >> 5;

    float4 pf[8];
    auto load_pf = [&](int tt) {
        #pragma unroll
        for (int k = 0; k < 8; k++) {
            const int m = tt * TILE_M + row0 + k * 8;
            pf[k] = (tt < n_tiles && m < n_nodes)
                  ? __ldcs(&h4[(size_t)m * 32 + c4])
                  : make_float4(0.f, 0.f, 0.f, 0.f);
        }
    };
    auto sts_pf = [&](uint16_t* buf) {
        #pragma unroll
        for (int k = 0; k < 8; k++)
            *reinterpret_cast<uint2*>(buf + (row0 + k * 8) * PADK + c4 * 4) =
                make_uint2(packh2(pf[k].x, pf[k].y), packh2(pf[k].z, pf[k].w));
    };

    int t = blockIdx.x;
    if (t < n_tiles) {
        load_pf(t);
        sts_pf(Ah);
    }
    __syncthreads();

    int buf = 0;
    while (t < n_tiles) {
        const int tn = t + (int)gridDim.x;
        load_pf(tn);                       // prefetch overlaps the MMA phase

        const uint32_t abase = (uint32_t)buf * (A_ELEMS * 2);
        float acc[2][8][4];
        #pragma unroll
        for (int mt = 0; mt < 2; mt++)
            #pragma unroll
            for (int nt = 0; nt < 8; nt++)
                #pragma unroll
                for (int r = 0; r < 4; r++) acc[mt][nt][r] = 0.f;

        #pragma unroll
        for (int kb = 0; kb < 8; kb++) {
            const uint32_t ko = (uint32_t)kb * 32;
            uint32_t ah[2][4];
            #pragma unroll
            for (int mt = 0; mt < 2; mt++)
                LDM_X4(ah[mt][0], ah[mt][1], ah[mt][2], ah[mt][3],
                       a_addr0[mt] + abase + ko);
            uint32_t bh[8][2];
            #pragma unroll
            for (int p = 0; p < 4; p++)
                LDM_X4(bh[2*p][0], bh[2*p][1], bh[2*p+1][0], bh[2*p+1][1], b_addr[p] + ko);
            #pragma unroll
            for (int mt = 0; mt < 2; mt++)
                #pragma unroll
                for (int nt = 0; nt < 8; nt++)
                    hmma(acc[mt][nt], ah[mt], bh[nt]);
        }

        const int m0 = t * TILE_M;
        #pragma unroll
        for (int mt = 0; mt < 2; mt++) {
            const int r0 = m0 + mwarp + mt * 16 + g;
            const int r1 = r0 + 8;
            #pragma unroll
            for (int c = 0; c < 2; c++) {
                uint4 s0, s1;
                __half2* h0 = reinterpret_cast<__half2*>(&s0);
                __half2* h1 = reinterpret_cast<__half2*>(&s1);
                #pragma unroll
                for (int q = 0; q < 4; q++) {
                    const int nt = c * 4 + q;
                    const int bcol = (nwarp + nt * 8 + tig * 2) & (HID - 1);
                    const float2 bb = *reinterpret_cast<const float2*>(&b1s[bcol]);
                    h0[q] = __floats2half2_rn(acc[mt][nt][0] + bb.x, acc[mt][nt][1] + bb.y);
                    h1[q] = __floats2half2_rn(acc[mt][nt][2] + bb.x, acc[mt][nt][3] + bb.y);
                }
                const uint32_t off = (uint32_t)nwarp + c * 32 + tig * 8;
                if (r0 < n_nodes) stg_pol(g_Yh + (size_t)r0 * NCOL + off, s0, pol);
                if (r1 < n_nodes) stg_pol(g_Yh + (size_t)r1 * NCOL + off, s1, pol);
            }
        }

        sts_pf(buf ? Ah : Ah + A_ELEMS);   // fill the other buffer
        __syncthreads();
        buf ^= 1;
        t = tn;
    }
}

// ---------------------------------------------------------------------------
// K2: 8 lanes/edge, 8 edges per warp-iteration, half2 math, plain loads.
// Single resident wave: 888 CTAs x 128 threads (12 CTAs/SM), grid-stride.
// ---------------------------------------------------------------------------
__global__ __launch_bounds__(K2_BLOCK, 12)
void edge_kernel(const int* __restrict__ src,
                 const int* __restrict__ dst,
                 const float* __restrict__ W2,
                 const float* __restrict__ b2,
                 const float* __restrict__ W3,
                 const float* __restrict__ b3,
                 float* __restrict__ out,
                 int E)
{
    const int lane = threadIdx.x & 31;
    const int sub  = lane >> 3;
    const int l8   = lane & 7;
    const int wid  = (blockIdx.x * blockDim.x + threadIdx.x) >> 5;
    const int nwarps = (gridDim.x * blockDim.x) >> 5;

    // lane features (physical within-half): i<4 -> q=l8*8+i*2 ; i>=4 -> q=64+l8*8+(i-4)*2
    __half2 w2h[8];
    #pragma unroll
    for (int i = 0; i < 8; i++) {
        const int q   = (i < 4) ? (l8 * 8 + i * 2) : (64 + l8 * 8 + (i - 4) * 2);
        const int qnw = q >> 6, qc = (q >> 5) & 1, qtig = (q >> 3) & 3, qnt4 = (q >> 1) & 3;
        const int j   = qnw * 64 + (qc * 4 + qnt4) * 8 + qtig * 2;
        w2h[i] = __floats2half2_rn(W2[j], W2[j + 1]);
    }
    const float c2 = b2[0];
    const float w3 = W3[0];
    const float c3 = b3[0];
    const __half2 zero2 = __floats2half2_rn(0.f, 0.f);

    for (int e = wid * 8 + sub; ; e += nwarps * 8) {
        const int ebase = e - sub;
        if (ebase >= E) break;
        const int eA = (e < E) ? e : (E - 1);
        const int e2 = e + 4;
        const int eB = (e2 < E) ? e2 : (E - 1);

        const int sA = src[eA], dA = dst[eA];
        const int sB = src[eB], dB = dst[eB];

        const __half* YA_u = g_Yh + (uint32_t)sA * NCOL;
        const __half* YA_v = g_Yh + (uint32_t)dA * NCOL + HID;
        const __half* YB_u = g_Yh + (uint32_t)sB * NCOL;
        const __half* YB_v = g_Yh + (uint32_t)dB * NCOL + HID;

        uint4 ua0 = *reinterpret_cast<const uint4*>(YA_u + l8 * 8);
        uint4 ua1 = *reinterpret_cast<const uint4*>(YA_u + 64 + l8 * 8);
        uint4 va0 = *reinterpret_cast<const uint4*>(YA_v + l8 * 8);
        uint4 va1 = *reinterpret_cast<const uint4*>(YA_v + 64 + l8 * 8);
        uint4 ub0 = *reinterpret_cast<const uint4*>(YB_u + l8 * 8);
        uint4 ub1 = *reinterpret_cast<const uint4*>(YB_u + 64 + l8 * 8);
        uint4 vb0 = *reinterpret_cast<const uint4*>(YB_v + l8 * 8);
        uint4 vb1 = *reinterpret_cast<const uint4*>(YB_v + 64 + l8 * 8);

        const __half2* uhA0 = reinterpret_cast<const __half2*>(&ua0);
        const __half2* uhA1 = reinterpret_cast<const __half2*>(&ua1);
        const __half2* vhA0 = reinterpret_cast<const __half2*>(&va0);
        const __half2* vhA1 = reinterpret_cast<const __half2*>(&va1);
        const __half2* uhB0 = reinterpret_cast<const __half2*>(&ub0);
        const __half2* uhB1 = reinterpret_cast<const __half2*>(&ub1);
        const __half2* vhB0 = reinterpret_cast<const __half2*>(&vb0);
        const __half2* vhB1 = reinterpret_cast<const __half2*>(&vb1);

        __half2 accA = zero2, accB = zero2;
        #pragma unroll
        for (int i = 0; i < 4; i++) {
            __half2 xA = __hmax2(__hadd2(uhA0[i], vhA0[i]), zero2);
            accA = __hfma2(xA, w2h[i], accA);
            __half2 xB = __hmax2(__hadd2(uhB0[i], vhB0[i]), zero2);
            accB = __hfma2(xB, w2h[i], accB);
        }
        #pragma unroll
        for (int i = 0; i < 4; i++) {
            __half2 xA = __hmax2(__hadd2(uhA1[i], vhA1[i]), zero2);
            accA = __hfma2(xA, w2h[4 + i], accA);
            __half2 xB = __hmax2(__hadd2(uhB1[i], vhB1[i]), zero2);
            accB = __hfma2(xB, w2h[4 + i], accB);
        }

        float2 fA = __half22float2(accA);
        float2 fB = __half22float2(accB);
        float pA = fA.x + fA.y;
        float pB = fB.x + fB.y;

        pA += __shfl_xor_sync(0xFFFFFFFFu, pA, 1);
        pB += __shfl_xor_sync(0xFFFFFFFFu, pB, 1);
        pA += __shfl_xor_sync(0xFFFFFFFFu, pA, 2);
        pB += __shfl_xor_sync(0xFFFFFFFFu, pB, 2);
        pA += __shfl_xor_sync(0xFFFFFFFFu, pA, 4);
        pB += __shfl_xor_sync(0xFFFFFFFFu, pB, 4);

        if (l8 == 0) {
            if (e < E) {
                float s2 = fmaxf(pA + c2, 0.f);
                float s3 = fmaxf(fmaf(s2, w3, c3), 0.f);
                __stcs(&out[e], __fdividef(1.f, 1.f + __expf(-s3)));
            }
            if (e2 < E) {
                float s2 = fmaxf(pB + c2, 0.f);
                float s3 = fmaxf(fmaf(s2, w3, c3), 0.f);
                __stcs(&out[e2], __fdividef(1.f, 1.f + __expf(-s3)));
            }
        }
    }
}

// ---------------------------------------------------------------------------
extern "C" void kernel_launch(void* const* d_in, const int* in_sizes, int n_in,
                              void* d_out, int out_size)
{
    const float* h   = (const float*)d_in[0];
    const int*   src = (const int*)  d_in[1];
    const int*   dst = (const int*)  d_in[2];
    const float* W1  = (const float*)d_in[3];
    const float* b1  = (const float*)d_in[4];
    const float* W2  = (const float*)d_in[5];
    const float* b2  = (const float*)d_in[6];
    const float* W3  = (const float*)d_in[7];
    const float* b3  = (const float*)d_in[8];
    float* out = (float*)d_out;

    const int n_nodes = in_sizes[0] / HID;
    const int E       = in_sizes[1];
    const int n_tiles = (n_nodes + TILE_M - 1) / TILE_M;

    cudaFuncSetAttribute(precompute_mma,
                         cudaFuncAttributeMaxDynamicSharedMemorySize, SMEM_BYTES);

    precompute_mma<<<K1_GRID, 256, SMEM_BYTES>>>(h, W1, b1, n_nodes, n_tiles);
    edge_kernel<<<K2_GRID, K2_BLOCK>>>(src, dst, W2, b2, W3, b3, out, E);
}